// round 14
// baseline (speedup 1.0000x reference)
#include <cuda_runtime.h>
#include <cuda_bf16.h>
#include <math.h>
#include <cstdint>

#define BB 8
#define LL 16
#define T_TAB 65536
#define RMAX 256
#define N_PIX (RMAX * RMAX)
#define NCELLS 211538
#define MW_BLOCKS 3
#define DENS_BLOCKS 827   // ceil(211538/256)

#define WPITCH 40   // bf16 elements per smem row (80B) -> conflict-free LDSM

__constant__ int c_res[LL] = {16, 19, 23, 28, 34, 40, 49, 58,
                              70, 84, 102, 122, 147, 177, 213, 256};
__constant__ int c_off[LL] = {0, 256, 617, 1146, 1930, 3086, 4686, 7087,
                              10451, 15351, 22407, 32811, 47695, 69304, 100633, 146002};

// Dense (de-hashed) grids.
__device__ float2 g_dense[BB][NCELLS];

// Pre-split effective weights (bf16 hi/lo), ROW-MAJOR [out][in].
__device__ __nv_bfloat16 g_W0h[BB][32][32], g_W0l[BB][32][32];
__device__ __nv_bfloat16 g_W1h[BB][32][32], g_W1l[BB][32][32];
__device__ float g_W2[BB][3][32];

// ---------------------------------------------------------------------------
// Warp-level bf16 MMA + ldmatrix (baseline PTX)
// ---------------------------------------------------------------------------
__device__ __forceinline__ void mma16816(float* c,
                                         uint32_t a0, uint32_t a1, uint32_t a2, uint32_t a3,
                                         uint32_t b0, uint32_t b1) {
    asm volatile("mma.sync.aligned.m16n8k16.row.col.f32.bf16.bf16.f32 "
                 "{%0,%1,%2,%3}, {%4,%5,%6,%7}, {%8,%9}, {%0,%1,%2,%3};"
                 : "+f"(c[0]), "+f"(c[1]), "+f"(c[2]), "+f"(c[3])
                 : "r"(a0), "r"(a1), "r"(a2), "r"(a3), "r"(b0), "r"(b1));
}

__device__ __forceinline__ void ldsm_x4(uint32_t* d, const void* p) {
    const uint32_t saddr = (uint32_t)__cvta_generic_to_shared(p);
    asm volatile("ldmatrix.sync.aligned.m8n8.x4.shared.b16 {%0,%1,%2,%3}, [%4];"
                 : "=r"(d[0]), "=r"(d[1]), "=r"(d[2]), "=r"(d[3]) : "r"(saddr));
}

__device__ __forceinline__ uint32_t pack_bf16(float lo, float hi) {
    __nv_bfloat16 l = __float2bfloat16_rn(lo);
    __nv_bfloat16 h = __float2bfloat16_rn(hi);
    return ((uint32_t)__bfloat16_as_ushort(h) << 16) | (uint32_t)__bfloat16_as_ushort(l);
}

// ---------------------------------------------------------------------------
// Prepass: grid (MW_BLOCKS + DENS_BLOCKS, BB) x 256 threads.
// ---------------------------------------------------------------------------
__global__ void __launch_bounds__(256)
prepass_kernel(const float* __restrict__ tables,
               const float* __restrict__ s,
               const float* __restrict__ w0, const float* __restrict__ aw0, const float* __restrict__ ab0,
               const float* __restrict__ w1, const float* __restrict__ aw1, const float* __restrict__ ab1,
               const float* __restrict__ w2, const float* __restrict__ aw2, const float* __restrict__ ab2)
{
    const int b = blockIdx.y;
    const int tid = threadIdx.x;

    if (blockIdx.x >= MW_BLOCKS) {
        // ---- densify ----
        const int c = (blockIdx.x - MW_BLOCKS) * 256 + tid;
        if (c >= NCELLS) return;
        int l = 0;
        #pragma unroll
        for (int k = 1; k < LL; k++) l += (c >= c_off[k]);
        const int local = c - c_off[l];
        const int r = c_res[l];
        const int y = local / r;
        const int x = local - y * r;
        const unsigned idx = ((unsigned)x ^ ((unsigned)y * 2654435761u)) & 65535u;
        const float2* tab = (const float2*)tables + ((size_t)b * LL + l) * T_TAB;
        g_dense[b][c] = __ldg(tab + idx);
        return;
    }

    // ---- modweights for one layer ----
    const int layer = blockIdx.x;
    const int wid = tid >> 5, lane = tid & 31;
    __shared__ float st[32];

    const float* aw = (layer == 0) ? aw0 : (layer == 1) ? aw1 : aw2;
    const float* ab = (layer == 0) ? ab0 : (layer == 1) ? ab1 : ab2;

    {
        const float4* sv4 = (const float4*)(s + b * 512);
        #pragma unroll
        for (int rr = 0; rr < 4; rr++) {
            const int row = wid + rr * 8;
            const float4* rw4 = (const float4*)(aw + row * 512);
            float acc = 0.f;
            #pragma unroll
            for (int it = 0; it < 4; it++) {
                float4 a = __ldg(sv4 + it * 32 + lane);
                float4 w = __ldg(rw4 + it * 32 + lane);
                acc += a.x * w.x + a.y * w.y + a.z * w.z + a.w * w.w;
            }
            #pragma unroll
            for (int d = 16; d > 0; d >>= 1) acc += __shfl_xor_sync(0xFFFFFFFFu, acc, d);
            if (lane == 0) st[row] = acc + __ldg(ab + row);
        }
    }
    __syncthreads();

    if (layer == 2) {
        if (wid < 3) {
            const int j = wid;
            const float v = w2[j * 32 + lane] * st[lane];
            float ss = v * v;
            #pragma unroll
            for (int d = 16; d > 0; d >>= 1) ss += __shfl_xor_sync(0xFFFFFFFFu, ss, d);
            g_W2[b][j][lane] = v * rsqrtf(ss + 1e-8f);
        }
    } else {
        const float* w = (layer == 0) ? w0 : w1;
        #pragma unroll
        for (int rr = 0; rr < 4; rr++) {
            const int j = wid + rr * 8;
            const float v = w[j * 32 + lane] * st[lane];
            float ss = v * v;
            #pragma unroll
            for (int d = 16; d > 0; d >>= 1) ss += __shfl_xor_sync(0xFFFFFFFFu, ss, d);
            const float wv = v * rsqrtf(ss + 1e-8f);
            const __nv_bfloat16 hi = __float2bfloat16_rn(wv);
            const __nv_bfloat16 lo = __float2bfloat16_rn(wv - __bfloat162float(hi));
            if (layer == 0) { g_W0h[b][j][lane] = hi; g_W0l[b][j][lane] = lo; }
            else            { g_W1h[b][j][lane] = hi; g_W1l[b][j][lane] = lo; }
        }
    }
}

// ---------------------------------------------------------------------------
// Layer 0: A from SMEM via ldmatrix (feature tiles), B from SMEM.
// ---------------------------------------------------------------------------
__device__ __forceinline__ void mma_layer0(
    float C[2][4][4],
    const __nv_bfloat16 (*Fh)[WPITCH], const __nv_bfloat16 (*Fl)[WPITCH],
    const __nv_bfloat16 (*Wh)[WPITCH], const __nv_bfloat16 (*Wl)[WPITCH],
    int lane)
{
    const int quad = lane >> 3, qr = lane & 7;
    const int trow = qr + (quad & 1) * 8;
    const int tcol = (quad >> 1) * 8;

    #pragma unroll
    for (int kt = 0; kt < 2; kt++) {
        const int kc = kt * 16 + tcol;
        uint32_t Ah[2][4], Al[2][4], Bh[2][4], Bl[2][4];
        #pragma unroll
        for (int mt = 0; mt < 2; mt++) {
            ldsm_x4(Ah[mt], &Fh[mt * 16 + trow][kc]);
            ldsm_x4(Al[mt], &Fl[mt * 16 + trow][kc]);
        }
        #pragma unroll
        for (int ch = 0; ch < 2; ch++) {
            ldsm_x4(Bh[ch], &Wh[ch * 16 + trow][kc]);
            ldsm_x4(Bl[ch], &Wl[ch * 16 + trow][kc]);
        }
        #pragma unroll
        for (int ch = 0; ch < 2; ch++) {
            #pragma unroll
            for (int half = 0; half < 2; half++) {
                const int nt = ch * 2 + half;
                const uint32_t bh0 = Bh[ch][half], bh1 = Bh[ch][half + 2];
                const uint32_t bl0 = Bl[ch][half], bl1 = Bl[ch][half + 2];
                #pragma unroll
                for (int mt = 0; mt < 2; mt++) {
                    mma16816(C[mt][nt], Ah[mt][0], Ah[mt][1], Ah[mt][2], Ah[mt][3], bh0, bh1);
                    mma16816(C[mt][nt], Ah[mt][0], Ah[mt][1], Ah[mt][2], Ah[mt][3], bl0, bl1);
                    mma16816(C[mt][nt], Al[mt][0], Al[mt][1], Al[mt][2], Al[mt][3], bh0, bh1);
                }
            }
        }
    }
}

// ---------------------------------------------------------------------------
// Layer 1: A fragments supplied in REGISTERS (built from layer-0 C frags);
// B from SMEM via ldmatrix.
// ---------------------------------------------------------------------------
__device__ __forceinline__ void mma_layer1_reg(
    float C[2][4][4],
    const uint32_t Ah[2][2][4], const uint32_t Al[2][2][4],   // [mt][kt][4]
    const __nv_bfloat16 (*Wh)[WPITCH], const __nv_bfloat16 (*Wl)[WPITCH],
    int lane)
{
    const int quad = lane >> 3, qr = lane & 7;
    const int trow = qr + (quad & 1) * 8;
    const int tcol = (quad >> 1) * 8;

    #pragma unroll
    for (int kt = 0; kt < 2; kt++) {
        const int kc = kt * 16 + tcol;
        uint32_t Bh[2][4], Bl[2][4];
        #pragma unroll
        for (int ch = 0; ch < 2; ch++) {
            ldsm_x4(Bh[ch], &Wh[ch * 16 + trow][kc]);
            ldsm_x4(Bl[ch], &Wl[ch * 16 + trow][kc]);
        }
        #pragma unroll
        for (int ch = 0; ch < 2; ch++) {
            #pragma unroll
            for (int half = 0; half < 2; half++) {
                const int nt = ch * 2 + half;
                const uint32_t bh0 = Bh[ch][half], bh1 = Bh[ch][half + 2];
                const uint32_t bl0 = Bl[ch][half], bl1 = Bl[ch][half + 2];
                #pragma unroll
                for (int mt = 0; mt < 2; mt++) {
                    const uint32_t* a = Ah[mt][kt];
                    const uint32_t* al = Al[mt][kt];
                    mma16816(C[mt][nt], a[0], a[1], a[2], a[3], bh0, bh1);
                    mma16816(C[mt][nt], a[0], a[1], a[2], a[3], bl0, bl1);
                    mma16816(C[mt][nt], al[0], al[1], al[2], al[3], bh0, bh1);
                }
            }
        }
    }
}

// ---------------------------------------------------------------------------
// Fused kernel — 128 threads, 4 warps, warp = 32 consecutive x-pixels,
// grid (512, BB). Layer-1 A operand built in registers from layer-0 C frags
// (C m16n8 layout == A m16n8k16 layout along n->k).
// ---------------------------------------------------------------------------
__global__ void __launch_bounds__(128)
fused_kernel(const float* __restrict__ b0, const float* __restrict__ b1,
             const float* __restrict__ b2, float* __restrict__ out)
{
    __shared__ __nv_bfloat16 sW0h[32][WPITCH], sW0l[32][WPITCH];
    __shared__ __nv_bfloat16 sW1h[32][WPITCH], sW1l[32][WPITCH];
    __shared__ __nv_bfloat16 sFh[4][32][WPITCH], sFl[4][32][WPITCH];
    __shared__ float sB0[32], sB1[32], sB2[3], sW2[3][32];

    const int b = blockIdx.y;
    const int tid = threadIdx.x;
    const int wid = tid >> 5;
    const int lane = tid & 31;
    const int g = lane >> 2;
    const int tg = lane & 3;

    // Stage pre-split weights: pure uint32 copies.
    {
        const uint32_t* s0h = (const uint32_t*)g_W0h[b];
        const uint32_t* s0l = (const uint32_t*)g_W0l[b];
        const uint32_t* s1h = (const uint32_t*)g_W1h[b];
        const uint32_t* s1l = (const uint32_t*)g_W1l[b];
        #pragma unroll
        for (int e = tid; e < 512; e += 128) {
            const int row = e >> 4, c2 = (e & 15) * 2;
            *(uint32_t*)&sW0h[row][c2] = __ldg(s0h + e);
            *(uint32_t*)&sW0l[row][c2] = __ldg(s0l + e);
            *(uint32_t*)&sW1h[row][c2] = __ldg(s1h + e);
            *(uint32_t*)&sW1l[row][c2] = __ldg(s1l + e);
        }
    }
    if (tid < 32) { sB0[tid] = b0[tid]; sB1[tid] = b1[tid]; }
    if (tid < 3)  sB2[tid] = b2[tid];
    if (tid < 96) ((float*)sW2)[tid] = ((const float*)g_W2[b])[tid];
    __syncthreads();

    // Pixel mapping: warp = 32 consecutive x; block = 32x4 tile.
    const int pxbase = (blockIdx.x & 7) * 32;
    const int py = (blockIdx.x >> 3) * 4 + wid;
    const int px = pxbase + lane;
    const float cx = (px + 0.5f) * (1.0f / RMAX);
    const float cy = (py + 0.5f) * (1.0f / RMAX);

    const float2* dense = (const float2*)g_dense[b];

    // ---- encode ----
    float feat[32];
    #pragma unroll
    for (int l = 0; l < LL; l++) {
        const int r = c_res[l];
        const float rf = (float)(r - 1);
        const float fpx = cx * rf, fpy = cy * rf;
        const float fx0 = floorf(fpx), fy0 = floorf(fpy);
        const float fx = fpx - fx0, fy = fpy - fy0;
        const int a00 = c_off[l] + (int)fy0 * r + (int)fx0;
        const float2 q00 = __ldg(dense + a00);
        const float2 q10 = __ldg(dense + a00 + 1);
        const float2 q01 = __ldg(dense + a00 + r);
        const float2 q11 = __ldg(dense + a00 + r + 1);
        const float w00 = (1.f - fx) * (1.f - fy);
        const float w10 = fx * (1.f - fy);
        const float w01 = (1.f - fx) * fy;
        const float w11 = fx * fy;
        feat[2 * l]     = q00.x * w00 + q10.x * w10 + q01.x * w01 + q11.x * w11;
        feat[2 * l + 1] = q00.y * w00 + q10.y * w10 + q01.y * w01 + q11.y * w11;
    }

    // ---- split features -> per-warp SMEM (layer-0 A via ldmatrix) ----
    #pragma unroll
    for (int c = 0; c < 16; c++) {
        const float f0 = feat[2 * c], f1 = feat[2 * c + 1];
        const float h0 = __bfloat162float(__float2bfloat16_rn(f0));
        const float h1 = __bfloat162float(__float2bfloat16_rn(f1));
        *(uint32_t*)&sFh[wid][lane][2 * c] = pack_bf16(f0, f1);
        *(uint32_t*)&sFl[wid][lane][2 * c] = pack_bf16(f0 - h0, f1 - h1);
    }
    __syncwarp();

    // ---- layer 0 ----
    float C[2][4][4];
    #pragma unroll
    for (int mt = 0; mt < 2; mt++)
        #pragma unroll
        for (int nt = 0; nt < 4; nt++)
            #pragma unroll
            for (int k = 0; k < 4; k++) C[mt][nt][k] = 0.f;
    mma_layer0(C, sFh[wid], sFl[wid], sW0h, sW0l, lane);

    // ---- epilogue 0 IN REGISTERS: bias + ReLU + hi/lo split -> layer-1 A frags.
    // C[mt][nt] (m16n8) c0..c3 == A (m16n8k16) a-pairs: nt pairs (0,1)->kt 0,
    // (2,3)->kt 1; within a pair, chunk ch gives (a0,a1) [ch=0] / (a2,a3) [ch=1].
    uint32_t A1h[2][2][4], A1l[2][2][4];
    #pragma unroll
    for (int mt = 0; mt < 2; mt++) {
        #pragma unroll
        for (int kt = 0; kt < 2; kt++) {
            #pragma unroll
            for (int ch = 0; ch < 2; ch++) {
                const int nt = kt * 2 + ch;
                const int col = nt * 8 + 2 * tg;
                const float v0 = fmaxf(C[mt][nt][0] + sB0[col], 0.f);
                const float v1 = fmaxf(C[mt][nt][1] + sB0[col + 1], 0.f);
                const float v2 = fmaxf(C[mt][nt][2] + sB0[col], 0.f);
                const float v3 = fmaxf(C[mt][nt][3] + sB0[col + 1], 0.f);
                const float t0 = __bfloat162float(__float2bfloat16_rn(v0));
                const float t1 = __bfloat162float(__float2bfloat16_rn(v1));
                const float t2 = __bfloat162float(__float2bfloat16_rn(v2));
                const float t3 = __bfloat162float(__float2bfloat16_rn(v3));
                A1h[mt][kt][2 * ch]     = pack_bf16(v0, v1);
                A1h[mt][kt][2 * ch + 1] = pack_bf16(v2, v3);
                A1l[mt][kt][2 * ch]     = pack_bf16(v0 - t0, v1 - t1);
                A1l[mt][kt][2 * ch + 1] = pack_bf16(v2 - t2, v3 - t3);
            }
        }
    }

    // ---- layer 1 (A from registers) ----
    #pragma unroll
    for (int mt = 0; mt < 2; mt++)
        #pragma unroll
        for (int nt = 0; nt < 4; nt++)
            #pragma unroll
            for (int k = 0; k < 4; k++) C[mt][nt][k] = 0.f;
    mma_layer1_reg(C, A1h, A1l, sW1h, sW1l, lane);

    // ---- epilogue 1 + layer 2 (fp32) + tanh + output ----
    float po[3][4];
    #pragma unroll
    for (int cc = 0; cc < 3; cc++)
        #pragma unroll
        for (int k = 0; k < 4; k++) po[cc][k] = 0.f;

    #pragma unroll
    for (int mt = 0; mt < 2; mt++) {
        #pragma unroll
        for (int nt = 0; nt < 4; nt++) {
            const int col = nt * 8 + 2 * tg;
            const float h00 = fmaxf(C[mt][nt][0] + sB1[col], 0.f);
            const float h01 = fmaxf(C[mt][nt][1] + sB1[col + 1], 0.f);
            const float h10 = fmaxf(C[mt][nt][2] + sB1[col], 0.f);
            const float h11 = fmaxf(C[mt][nt][3] + sB1[col + 1], 0.f);
            #pragma unroll
            for (int cc = 0; cc < 3; cc++) {
                const float wv0 = sW2[cc][col];
                const float wv1 = sW2[cc][col + 1];
                po[cc][mt * 2]     += h00 * wv0 + h01 * wv1;
                po[cc][mt * 2 + 1] += h10 * wv0 + h11 * wv1;
            }
        }
    }
    #pragma unroll
    for (int cc = 0; cc < 3; cc++)
        #pragma unroll
        for (int k = 0; k < 4; k++) {
            po[cc][k] += __shfl_xor_sync(0xFFFFFFFFu, po[cc][k], 1);
            po[cc][k] += __shfl_xor_sync(0xFFFFFFFFu, po[cc][k], 2);
        }

    if (tg == 0) {
        #pragma unroll
        for (int mt = 0; mt < 2; mt++) {
            #pragma unroll
            for (int rh = 0; rh < 2; rh++) {
                const int row = mt * 16 + g + rh * 8;
                const size_t base = (size_t)b * 3 * N_PIX + (size_t)py * RMAX + (pxbase + row);
                #pragma unroll
                for (int cc = 0; cc < 3; cc++)
                    out[base + (size_t)cc * N_PIX] = tanhf(sB2[cc] + po[cc][mt * 2 + rh]);
            }
        }
    }
}

// ---------------------------------------------------------------------------
// Launch
// ---------------------------------------------------------------------------
extern "C" void kernel_launch(void* const* d_in, const int* in_sizes, int n_in,
                              void* d_out, int out_size)
{
    const float* x   = (const float*)d_in[0];
    const float* s   = (const float*)d_in[1];
    const float* w0  = (const float*)d_in[3];
    const float* aw0 = (const float*)d_in[4];
    const float* ab0 = (const float*)d_in[5];
    const float* b0  = (const float*)d_in[6];
    const float* w1  = (const float*)d_in[7];
    const float* aw1 = (const float*)d_in[8];
    const float* ab1 = (const float*)d_in[9];
    const float* b1  = (const float*)d_in[10];
    const float* w2  = (const float*)d_in[11];
    const float* aw2 = (const float*)d_in[12];
    const float* ab2 = (const float*)d_in[13];
    const float* b2  = (const float*)d_in[14];
    float* out = (float*)d_out;

    prepass_kernel<<<dim3(MW_BLOCKS + DENS_BLOCKS, BB), 256>>>(
        x, s, w0, aw0, ab0, w1, aw1, ab1, w2, aw2, ab2);
    fused_kernel<<<dim3(512, BB), 128>>>(b0, b1, b2, out);
}

// round 16
// speedup vs baseline: 1.0375x; 1.0375x over previous
#include <cuda_runtime.h>
#include <cuda_bf16.h>
#include <math.h>
#include <cstdint>

#define BB 8
#define LL 16
#define T_TAB 65536
#define RMAX 256
#define N_PIX (RMAX * RMAX)
#define NCELLS 211538
#define MW_BLOCKS 3
#define DENS_BLOCKS 827   // ceil(211538/256)

#define WPITCH 40   // bf16/row (80B): 16B-aligned rows (ldmatrix req), conflict-free

__constant__ int c_res[LL] = {16, 19, 23, 28, 34, 40, 49, 58,
                              70, 84, 102, 122, 147, 177, 213, 256};
__constant__ int c_off[LL] = {0, 256, 617, 1146, 1930, 3086, 4686, 7087,
                              10451, 15351, 22407, 32811, 47695, 69304, 100633, 146002};

// Dense (de-hashed) grids.
__device__ float2 g_dense[BB][NCELLS];

// Pre-split effective weights (bf16 hi/lo), ROW-MAJOR [out][in].
__device__ __nv_bfloat16 g_W0h[BB][32][32], g_W0l[BB][32][32];
__device__ __nv_bfloat16 g_W1h[BB][32][32], g_W1l[BB][32][32];
__device__ float g_W2[BB][3][32];

// ---------------------------------------------------------------------------
// Warp-level bf16 MMA + ldmatrix + packed converts (baseline PTX)
// ---------------------------------------------------------------------------
__device__ __forceinline__ void mma16816(float* c,
                                         uint32_t a0, uint32_t a1, uint32_t a2, uint32_t a3,
                                         uint32_t b0, uint32_t b1) {
    asm volatile("mma.sync.aligned.m16n8k16.row.col.f32.bf16.bf16.f32 "
                 "{%0,%1,%2,%3}, {%4,%5,%6,%7}, {%8,%9}, {%0,%1,%2,%3};"
                 : "+f"(c[0]), "+f"(c[1]), "+f"(c[2]), "+f"(c[3])
                 : "r"(a0), "r"(a1), "r"(a2), "r"(a3), "r"(b0), "r"(b1));
}

__device__ __forceinline__ void ldsm_x4(uint32_t* d, const void* p) {
    const uint32_t saddr = (uint32_t)__cvta_generic_to_shared(p);
    asm volatile("ldmatrix.sync.aligned.m8n8.x4.shared.b16 {%0,%1,%2,%3}, [%4];"
                 : "=r"(d[0]), "=r"(d[1]), "=r"(d[2]), "=r"(d[3]) : "r"(saddr));
}

// Packed bf16x2 convert: low16 = cvt(lo), high16 = cvt(hi). One instruction.
__device__ __forceinline__ uint32_t cvt2bf(float lo, float hi) {
    uint32_t r;
    asm("cvt.rn.bf16x2.f32 %0, %1, %2;" : "=r"(r) : "f"(hi), "f"(lo));
    return r;
}
// Unpack bf16x2 -> two fp32.
__device__ __forceinline__ void bf2f(uint32_t u, float& lo, float& hi) {
    __nv_bfloat162 h2 = *(__nv_bfloat162*)&u;
    float2 f = __bfloat1622float2(h2);
    lo = f.x; hi = f.y;
}

// ---------------------------------------------------------------------------
// Prepass: grid (MW_BLOCKS + DENS_BLOCKS, BB) x 256 threads.
// ---------------------------------------------------------------------------
__global__ void __launch_bounds__(256)
prepass_kernel(const float* __restrict__ tables,
               const float* __restrict__ s,
               const float* __restrict__ w0, const float* __restrict__ aw0, const float* __restrict__ ab0,
               const float* __restrict__ w1, const float* __restrict__ aw1, const float* __restrict__ ab1,
               const float* __restrict__ w2, const float* __restrict__ aw2, const float* __restrict__ ab2)
{
    const int b = blockIdx.y;
    const int tid = threadIdx.x;

    if (blockIdx.x >= MW_BLOCKS) {
        // ---- densify ----
        const int c = (blockIdx.x - MW_BLOCKS) * 256 + tid;
        if (c >= NCELLS) return;
        int l = 0;
        #pragma unroll
        for (int k = 1; k < LL; k++) l += (c >= c_off[k]);
        const int local = c - c_off[l];
        const int r = c_res[l];
        const int y = local / r;
        const int x = local - y * r;
        const unsigned idx = ((unsigned)x ^ ((unsigned)y * 2654435761u)) & 65535u;
        const float2* tab = (const float2*)tables + ((size_t)b * LL + l) * T_TAB;
        g_dense[b][c] = __ldg(tab + idx);
        return;
    }

    // ---- modweights for one layer ----
    const int layer = blockIdx.x;
    const int wid = tid >> 5, lane = tid & 31;
    __shared__ float st[32];

    const float* aw = (layer == 0) ? aw0 : (layer == 1) ? aw1 : aw2;
    const float* ab = (layer == 0) ? ab0 : (layer == 1) ? ab1 : ab2;

    {
        const float4* sv4 = (const float4*)(s + b * 512);
        #pragma unroll
        for (int rr = 0; rr < 4; rr++) {
            const int row = wid + rr * 8;
            const float4* rw4 = (const float4*)(aw + row * 512);
            float acc = 0.f;
            #pragma unroll
            for (int it = 0; it < 4; it++) {
                float4 a = __ldg(sv4 + it * 32 + lane);
                float4 w = __ldg(rw4 + it * 32 + lane);
                acc += a.x * w.x + a.y * w.y + a.z * w.z + a.w * w.w;
            }
            #pragma unroll
            for (int d = 16; d > 0; d >>= 1) acc += __shfl_xor_sync(0xFFFFFFFFu, acc, d);
            if (lane == 0) st[row] = acc + __ldg(ab + row);
        }
    }
    __syncthreads();

    if (layer == 2) {
        if (wid < 3) {
            const int j = wid;
            const float v = w2[j * 32 + lane] * st[lane];
            float ss = v * v;
            #pragma unroll
            for (int d = 16; d > 0; d >>= 1) ss += __shfl_xor_sync(0xFFFFFFFFu, ss, d);
            g_W2[b][j][lane] = v * rsqrtf(ss + 1e-8f);
        }
    } else {
        const float* w = (layer == 0) ? w0 : w1;
        #pragma unroll
        for (int rr = 0; rr < 4; rr++) {
            const int j = wid + rr * 8;
            const float v = w[j * 32 + lane] * st[lane];
            float ss = v * v;
            #pragma unroll
            for (int d = 16; d > 0; d >>= 1) ss += __shfl_xor_sync(0xFFFFFFFFu, ss, d);
            const float wv = v * rsqrtf(ss + 1e-8f);
            const __nv_bfloat16 hi = __float2bfloat16_rn(wv);
            const __nv_bfloat16 lo = __float2bfloat16_rn(wv - __bfloat162float(hi));
            if (layer == 0) { g_W0h[b][j][lane] = hi; g_W0l[b][j][lane] = lo; }
            else            { g_W1h[b][j][lane] = hi; g_W1l[b][j][lane] = lo; }
        }
    }
}

// ---------------------------------------------------------------------------
// One MMA layer, ldmatrix-based (R13 verified layout).
// ---------------------------------------------------------------------------
__device__ __forceinline__ void mma_layer(
    float C[2][4][4],
    const __nv_bfloat16 (*Fh)[WPITCH], const __nv_bfloat16 (*Fl)[WPITCH],
    const __nv_bfloat16 (*Wh)[WPITCH], const __nv_bfloat16 (*Wl)[WPITCH],
    int lane)
{
    const int quad = lane >> 3, qr = lane & 7;
    const int trow = qr + (quad & 1) * 8;
    const int tcol = (quad >> 1) * 8;

    #pragma unroll
    for (int kt = 0; kt < 2; kt++) {
        const int kc = kt * 16 + tcol;
        uint32_t Ah[2][4], Al[2][4], Bh[2][4], Bl[2][4];
        #pragma unroll
        for (int mt = 0; mt < 2; mt++) {
            ldsm_x4(Ah[mt], &Fh[mt * 16 + trow][kc]);
            ldsm_x4(Al[mt], &Fl[mt * 16 + trow][kc]);
        }
        #pragma unroll
        for (int ch = 0; ch < 2; ch++) {
            ldsm_x4(Bh[ch], &Wh[ch * 16 + trow][kc]);
            ldsm_x4(Bl[ch], &Wl[ch * 16 + trow][kc]);
        }
        #pragma unroll
        for (int ch = 0; ch < 2; ch++) {
            #pragma unroll
            for (int half = 0; half < 2; half++) {
                const int nt = ch * 2 + half;
                const uint32_t bh0 = Bh[ch][half], bh1 = Bh[ch][half + 2];
                const uint32_t bl0 = Bl[ch][half], bl1 = Bl[ch][half + 2];
                #pragma unroll
                for (int mt = 0; mt < 2; mt++) {
                    mma16816(C[mt][nt], Ah[mt][0], Ah[mt][1], Ah[mt][2], Ah[mt][3], bh0, bh1);
                    mma16816(C[mt][nt], Ah[mt][0], Ah[mt][1], Ah[mt][2], Ah[mt][3], bl0, bl1);
                    mma16816(C[mt][nt], Al[mt][0], Al[mt][1], Al[mt][2], Al[mt][3], bh0, bh1);
                }
            }
        }
    }
}

// ---------------------------------------------------------------------------
// Fused kernel — R13 structure (128 threads, 4 warps, warp = 32 consecutive
// x-pixels, grid (512, BB)). Deltas vs R13: per-level feature split (no feat
// array) + bf16x2 packed converts. WPITCH stays 40 (ldmatrix 16B alignment).
// ---------------------------------------------------------------------------
__global__ void __launch_bounds__(128)
fused_kernel(const float* __restrict__ b0, const float* __restrict__ b1,
             const float* __restrict__ b2, float* __restrict__ out)
{
    __shared__ __nv_bfloat16 sW0h[32][WPITCH], sW0l[32][WPITCH];
    __shared__ __nv_bfloat16 sW1h[32][WPITCH], sW1l[32][WPITCH];
    __shared__ __nv_bfloat16 sFh[4][32][WPITCH], sFl[4][32][WPITCH];
    __shared__ float sB0[32], sB1[32], sB2[3], sW2[3][32];

    const int b = blockIdx.y;
    const int tid = threadIdx.x;
    const int wid = tid >> 5;
    const int lane = tid & 31;
    const int g = lane >> 2;
    const int tg = lane & 3;

    // Stage pre-split weights: pure uint32 copies.
    {
        const uint32_t* s0h = (const uint32_t*)g_W0h[b];
        const uint32_t* s0l = (const uint32_t*)g_W0l[b];
        const uint32_t* s1h = (const uint32_t*)g_W1h[b];
        const uint32_t* s1l = (const uint32_t*)g_W1l[b];
        #pragma unroll
        for (int e = tid; e < 512; e += 128) {
            const int row = e >> 4, c2 = (e & 15) * 2;
            *(uint32_t*)&sW0h[row][c2] = __ldg(s0h + e);
            *(uint32_t*)&sW0l[row][c2] = __ldg(s0l + e);
            *(uint32_t*)&sW1h[row][c2] = __ldg(s1h + e);
            *(uint32_t*)&sW1l[row][c2] = __ldg(s1l + e);
        }
    }
    if (tid < 32) { sB0[tid] = b0[tid]; sB1[tid] = b1[tid]; }
    if (tid < 3)  sB2[tid] = b2[tid];
    if (tid < 96) ((float*)sW2)[tid] = ((const float*)g_W2[b])[tid];
    __syncthreads();

    // Pixel mapping: warp = 32 consecutive x; block = 32x4 tile.
    const int pxbase = (blockIdx.x & 7) * 32;
    const int py = (blockIdx.x >> 3) * 4 + wid;
    const int px = pxbase + lane;
    const float cx = (px + 0.5f) * (1.0f / RMAX);
    const float cy = (py + 0.5f) * (1.0f / RMAX);

    const float2* dense = (const float2*)g_dense[b];

    // ---- encode: per-level interp -> immediate hi/lo split -> SMEM ----
    #pragma unroll
    for (int l = 0; l < LL; l++) {
        const int r = c_res[l];
        const float rf = (float)(r - 1);
        const float fpx = cx * rf, fpy = cy * rf;
        const float fx0 = floorf(fpx), fy0 = floorf(fpy);
        const float fx = fpx - fx0, fy = fpy - fy0;
        const int a00 = c_off[l] + (int)fy0 * r + (int)fx0;
        const float2 q00 = __ldg(dense + a00);
        const float2 q10 = __ldg(dense + a00 + 1);
        const float2 q01 = __ldg(dense + a00 + r);
        const float2 q11 = __ldg(dense + a00 + r + 1);
        const float w00 = (1.f - fx) * (1.f - fy);
        const float w10 = fx * (1.f - fy);
        const float w01 = (1.f - fx) * fy;
        const float w11 = fx * fy;
        const float f0 = q00.x * w00 + q10.x * w10 + q01.x * w01 + q11.x * w11;
        const float f1 = q00.y * w00 + q10.y * w10 + q01.y * w01 + q11.y * w11;
        const uint32_t hi = cvt2bf(f0, f1);
        float t0, t1; bf2f(hi, t0, t1);
        const uint32_t lo = cvt2bf(f0 - t0, f1 - t1);
        *(uint32_t*)&sFh[wid][lane][2 * l] = hi;
        *(uint32_t*)&sFl[wid][lane][2 * l] = lo;
    }
    __syncwarp();

    // ---- layer 0 ----
    float C[2][4][4];
    #pragma unroll
    for (int mt = 0; mt < 2; mt++)
        #pragma unroll
        for (int nt = 0; nt < 4; nt++)
            #pragma unroll
            for (int k = 0; k < 4; k++) C[mt][nt][k] = 0.f;
    mma_layer(C, sFh[wid], sFl[wid], sW0h, sW0l, lane);
    __syncwarp();

    // ---- epilogue 0: bias + ReLU, re-split (bf16x2 cvt) ----
    #pragma unroll
    for (int mt = 0; mt < 2; mt++) {
        #pragma unroll
        for (int nt = 0; nt < 4; nt++) {
            const int col = nt * 8 + 2 * tg;
            const float v0 = fmaxf(C[mt][nt][0] + sB0[col], 0.f);
            const float v1 = fmaxf(C[mt][nt][1] + sB0[col + 1], 0.f);
            const float v2 = fmaxf(C[mt][nt][2] + sB0[col], 0.f);
            const float v3 = fmaxf(C[mt][nt][3] + sB0[col + 1], 0.f);
            const int r0 = mt * 16 + g, r1 = mt * 16 + g + 8;
            const uint32_t hi0 = cvt2bf(v0, v1);
            const uint32_t hi1 = cvt2bf(v2, v3);
            float t0, t1, t2, t3;
            bf2f(hi0, t0, t1);
            bf2f(hi1, t2, t3);
            *(uint32_t*)&sFh[wid][r0][col] = hi0;
            *(uint32_t*)&sFh[wid][r1][col] = hi1;
            *(uint32_t*)&sFl[wid][r0][col] = cvt2bf(v0 - t0, v1 - t1);
            *(uint32_t*)&sFl[wid][r1][col] = cvt2bf(v2 - t2, v3 - t3);
        }
    }
    __syncwarp();

    // ---- layer 1 ----
    #pragma unroll
    for (int mt = 0; mt < 2; mt++)
        #pragma unroll
        for (int nt = 0; nt < 4; nt++)
            #pragma unroll
            for (int k = 0; k < 4; k++) C[mt][nt][k] = 0.f;
    mma_layer(C, sFh[wid], sFl[wid], sW1h, sW1l, lane);

    // ---- epilogue 1 + layer 2 (fp32) + tanh + output ----
    float po[3][4];
    #pragma unroll
    for (int cc = 0; cc < 3; cc++)
        #pragma unroll
        for (int k = 0; k < 4; k++) po[cc][k] = 0.f;

    #pragma unroll
    for (int mt = 0; mt < 2; mt++) {
        #pragma unroll
        for (int nt = 0; nt < 4; nt++) {
            const int col = nt * 8 + 2 * tg;
            const float h00 = fmaxf(C[mt][nt][0] + sB1[col], 0.f);
            const float h01 = fmaxf(C[mt][nt][1] + sB1[col + 1], 0.f);
            const float h10 = fmaxf(C[mt][nt][2] + sB1[col], 0.f);
            const float h11 = fmaxf(C[mt][nt][3] + sB1[col + 1], 0.f);
            #pragma unroll
            for (int cc = 0; cc < 3; cc++) {
                const float wv0 = sW2[cc][col];
                const float wv1 = sW2[cc][col + 1];
                po[cc][mt * 2]     += h00 * wv0 + h01 * wv1;
                po[cc][mt * 2 + 1] += h10 * wv0 + h11 * wv1;
            }
        }
    }
    #pragma unroll
    for (int cc = 0; cc < 3; cc++)
        #pragma unroll
        for (int k = 0; k < 4; k++) {
            po[cc][k] += __shfl_xor_sync(0xFFFFFFFFu, po[cc][k], 1);
            po[cc][k] += __shfl_xor_sync(0xFFFFFFFFu, po[cc][k], 2);
        }

    if (tg == 0) {
        #pragma unroll
        for (int mt = 0; mt < 2; mt++) {
            #pragma unroll
            for (int rh = 0; rh < 2; rh++) {
                const int row = mt * 16 + g + rh * 8;
                const size_t base = (size_t)b * 3 * N_PIX + (size_t)py * RMAX + (pxbase + row);
                #pragma unroll
                for (int cc = 0; cc < 3; cc++)
                    out[base + (size_t)cc * N_PIX] = tanhf(sB2[cc] + po[cc][mt * 2 + rh]);
            }
        }
    }
}

// ---------------------------------------------------------------------------
// Launch
// ---------------------------------------------------------------------------
extern "C" void kernel_launch(void* const* d_in, const int* in_sizes, int n_in,
                              void* d_out, int out_size)
{
    const float* x   = (const float*)d_in[0];
    const float* s   = (const float*)d_in[1];
    const float* w0  = (const float*)d_in[3];
    const float* aw0 = (const float*)d_in[4];
    const float* ab0 = (const float*)d_in[5];
    const float* b0  = (const float*)d_in[6];
    const float* w1  = (const float*)d_in[7];
    const float* aw1 = (const float*)d_in[8];
    const float* ab1 = (const float*)d_in[9];
    const float* b1  = (const float*)d_in[10];
    const float* w2  = (const float*)d_in[11];
    const float* aw2 = (const float*)d_in[12];
    const float* ab2 = (const float*)d_in[13];
    const float* b2  = (const float*)d_in[14];
    float* out = (float*)d_out;

    prepass_kernel<<<dim3(MW_BLOCKS + DENS_BLOCKS, BB), 256>>>(
        x, s, w0, aw0, ab0, w1, aw1, ab1, w2, aw2, ab2);
    fused_kernel<<<dim3(512, BB), 128>>>(b0, b1, b2, out);
}